// round 11
// baseline (speedup 1.0000x reference)
#include <cuda_runtime.h>

#define NPTS   8192
#define BATCH  4
#define M      2048
#define KNN    32
#define CF     32
#define R2     0.04f

typedef unsigned long long ull;

// scratch (no allocations allowed)
__device__ int   g_idx[BATCH * M * KNN];
#define WTOT (35*64 + 64*64 + 64*128 + 64 + 64 + 128)   // 14784
__device__ float g_w[WTOT];
// h1 staging: [gw (8192)][channel-pair (32)][neighbor lane (32)], packed f32x2
__device__ ull   g_h1[(size_t)BATCH * M * 32 * 32];
// spatially sorted points (Morton-cell order) + original indices
__device__ float g_sx[BATCH * NPTS], g_sy[BATCH * NPTS], g_sz[BATCH * NPTS];
__device__ int   g_si[BATCH * NPTS];

// ---- packed f32x2 helpers (bit-identical IEEE f32 per lane) ----------------
__device__ __forceinline__ ull f2pack(float a, float b) {
    ull r; asm("mov.b64 %0, {%1,%2};" : "=l"(r) : "f"(a), "f"(b)); return r;
}
__device__ __forceinline__ void f2unpack(ull v, float& a, float& b) {
    asm("mov.b64 {%0,%1}, %2;" : "=f"(a), "=f"(b) : "l"(v));
}
#define F2ADD(d, a, b)    asm("add.rn.f32x2 %0, %1, %2;"     : "=l"(d) : "l"(a), "l"(b))
#define F2MUL(d, a, b)    asm("mul.rn.f32x2 %0, %1, %2;"     : "=l"(d) : "l"(a), "l"(b))
#define F2FMA(d, a, b, c) asm("fma.rn.f32x2 %0, %1, %2, %3;" : "=l"(d) : "l"(a), "l"(b), "l"(c))

__device__ __forceinline__ unsigned redux_max_u32(unsigned v) {
    unsigned r; asm("redux.sync.max.u32 %0, %1, 0xffffffff;" : "=r"(r) : "r"(v)); return r;
}
__device__ __forceinline__ unsigned redux_min_u32(unsigned v) {
    unsigned r; asm("redux.sync.min.u32 %0, %1, 0xffffffff;" : "=r"(r) : "r"(v)); return r;
}

__device__ __forceinline__ unsigned spread3_4(unsigned v) {  // 4 bits -> every 3rd
    unsigned r = (v & 1u);
    r |= (v & 2u) << 2;
    r |= (v & 4u) << 4;
    r |= (v & 8u) << 6;
    return r;
}

// ---------------------------------------------------------------------------
// Kernel 0: spatial bucket sort. One block per batch. 16^3 grid in Morton
// order; counting sort via smem histogram + block scan + atomic scatter.
// ---------------------------------------------------------------------------
__global__ __launch_bounds__(1024, 1) void sort_kernel(const float* __restrict__ coords)
{
    __shared__ int cnt[4096];
    __shared__ int ss[1024];
    const int b = blockIdx.x, tid = threadIdx.x;
    const float* X = coords + (size_t)b * 3 * NPTS;
    const float* Y = X + NPTS;
    const float* Z = X + 2 * NPTS;

    for (int i = tid; i < 4096; i += 1024) cnt[i] = 0;
    __syncthreads();

    int cell8[8];
#pragma unroll
    for (int i = 0; i < 8; i++) {
        int n = tid + i * 1024;
        int cx = min(15, (int)(X[n] * 16.0f));
        int cy = min(15, (int)(Y[n] * 16.0f));
        int cz = min(15, (int)(Z[n] * 16.0f));
        int cell = spread3_4(cx) | (spread3_4(cy) << 1) | (spread3_4(cz) << 2);
        cell8[i] = cell;
        atomicAdd(&cnt[cell], 1);
    }
    __syncthreads();

    int l0 = cnt[4 * tid], l1 = cnt[4 * tid + 1], l2 = cnt[4 * tid + 2], l3 = cnt[4 * tid + 3];
    int local = l0 + l1 + l2 + l3;
    ss[tid] = local;
    __syncthreads();
    for (int off = 1; off < 1024; off <<= 1) {
        int v = (tid >= off) ? ss[tid - off] : 0;
        __syncthreads();
        ss[tid] += v;
        __syncthreads();
    }
    int ex = ss[tid] - local;
    cnt[4 * tid]     = ex;
    cnt[4 * tid + 1] = ex + l0;
    cnt[4 * tid + 2] = ex + l0 + l1;
    cnt[4 * tid + 3] = ex + l0 + l1 + l2;
    __syncthreads();

#pragma unroll
    for (int i = 0; i < 8; i++) {
        int n = tid + i * 1024;
        int pos = atomicAdd(&cnt[cell8[i]], 1);
        g_sx[b * NPTS + pos] = X[n];
        g_sy[b * NPTS + pos] = Y[n];
        g_sz[b * NPTS + pos] = Z[n];
        g_si[b * NPTS + pos] = n;
    }
}

// ---------------------------------------------------------------------------
// Kernel 1: furthest point sampling with exact THREAD-level spatial pruning.
// 1024 threads, 8 spatially-contiguous points/thread (tighter bboxes ->
// higher prune rate; shorter active-warp critical path: 4 pair-groups,
// depth-3 max tree, 8-wide index scan). Stage 2 = round-9 proven design:
// per-warp key STS -> single barrier -> every warp redundantly reduces the
// 32 warp keys (redux.max dist bits + redux.min masked original index).
// Skip test (lb2*0.999 > bm) provably leaves dl bit-exact when it fires.
// ---------------------------------------------------------------------------
__global__ __launch_bounds__(1024, 1) void fps_kernel(
    const float* __restrict__ coords, float* __restrict__ centers)
{
    const int b = blockIdx.x, tid = threadIdx.x;
    const int wid = tid >> 5, lane = tid & 31;
    const float* X = coords + (size_t)b * 3 * NPTS;
    const float* Y = X + NPTS;
    const float* Z = X + 2 * NPTS;
    const float* SX = g_sx + b * NPTS;
    const float* SY = g_sy + b * NPTS;
    const float* SZ = g_sz + b * NPTS;
    const int*   SI = g_si + b * NPTS;

    ull px2[4], py2[4], pz2[4];
    int oi[8];
    float dl[8];
    float bxmin = 1e30f, bxmax = -1e30f, bymin = 1e30f, bymax = -1e30f,
          bzmin = 1e30f, bzmax = -1e30f;
    const int base = tid * 8;
#pragma unroll
    for (int j = 0; j < 4; j++) {
        float x0 = SX[base + 2*j], x1 = SX[base + 2*j + 1];
        float y0 = SY[base + 2*j], y1 = SY[base + 2*j + 1];
        float z0 = SZ[base + 2*j], z1 = SZ[base + 2*j + 1];
        px2[j] = f2pack(x0, x1); py2[j] = f2pack(y0, y1); pz2[j] = f2pack(z0, z1);
        oi[2*j] = SI[base + 2*j]; oi[2*j + 1] = SI[base + 2*j + 1];
        dl[2*j] = 1e30f; dl[2*j + 1] = 1e30f;
        bxmin = fminf(bxmin, fminf(x0, x1)); bxmax = fmaxf(bxmax, fmaxf(x0, x1));
        bymin = fminf(bymin, fminf(y0, y1)); bymax = fmaxf(bymax, fmaxf(y0, y1));
        bzmin = fminf(bzmin, fminf(z0, z1)); bzmax = fmaxf(bzmax, fmaxf(z0, z1));
    }

    __shared__ ull skey[2][32];

    float* ox = centers + (size_t)b * 3 * M;
    float* oy = ox + M;
    float* oz = ox + 2 * M;

    float cx = __ldg(X), cy = __ldg(Y), cz = __ldg(Z);
    if (tid == 0) { ox[0] = cx; oy[0] = cy; oz[0] = cz; }

    float bm = 1e30f;            // cached thread-best distance (max of dl)
    int   bi = 0x7fffffff;       // cached thread-best original index

    for (int s = 0; s < M; s++) {
        // conservative lower bound on d2(c, any owned point)
        float tx = fmaxf(fmaxf(bxmin - cx, cx - bxmax), 0.0f);
        float ty = fmaxf(fmaxf(bymin - cy, cy - bymax), 0.0f);
        float tz = fmaxf(fmaxf(bzmin - cz, cz - bzmax), 0.0f);
        float lb2 = fmaf(tz, tz, fmaf(ty, ty, tx * tx));

        if (!(lb2 * 0.999f > bm)) {          // active: some dl may change
            const ull ncx = f2pack(-cx, -cx);
            const ull ncy = f2pack(-cy, -cy);
            const ull ncz = f2pack(-cz, -cz);
            // 1) distance updates (independent per pair)
#pragma unroll
            for (int j = 0; j < 4; j++) {
                ull dx, dy, dz, t;
                F2ADD(dx, px2[j], ncx);
                F2ADD(dy, py2[j], ncy);
                F2ADD(dz, pz2[j], ncz);
                F2MUL(t, dx, dx);
                F2FMA(t, dy, dy, t);
                F2FMA(t, dz, dz, t);
                float t0, t1; f2unpack(t, t0, t1);
                dl[2*j]     = fminf(dl[2*j],     t0);
                dl[2*j + 1] = fminf(dl[2*j + 1], t1);
            }
            // 2) max tree (depth 3)
            float m0 = fmaxf(dl[0], dl[1]), m1 = fmaxf(dl[2], dl[3]);
            float m2 = fmaxf(dl[4], dl[5]), m3 = fmaxf(dl[6], dl[7]);
            m0 = fmaxf(m0, m1); m2 = fmaxf(m2, m3);
            bm = fmaxf(m0, m2);
            // 3) lowest original index among dl==bm (independent predicated ops)
            int mi = 0x7fffffff;
#pragma unroll
            for (int k = 0; k < 8; k++)
                if (dl[k] == bm) mi = min(mi, oi[k]);
            bi = mi;
        }

        // stage 1: max distance bits, then min original index among ties
        unsigned mb = __float_as_uint(bm);          // bm >= 0 -> monotone bits
        unsigned wm = redux_max_u32(mb);
        unsigned ci = (mb == wm) ? (unsigned)bi : 0x7fffffffu;
        unsigned wi = redux_min_u32(ci);
        if (lane == 0) skey[s & 1][wid] = ((ull)wm << 32) | wi;
        __syncthreads();

        // stage 2: every warp reduces the 32 warp keys redundantly
        ull k = skey[s & 1][lane];
        unsigned v  = (unsigned)(k >> 32);
        unsigned ii = (unsigned)k;
        unsigned gm = redux_max_u32(v);
        unsigned c2 = (v == gm) ? ii : 0x7fffffffu;
        unsigned gi = redux_min_u32(c2);

        cx = __ldg(X + gi); cy = __ldg(Y + gi); cz = __ldg(Z + gi);
        if (tid == 0 && s + 1 < M) {
            ox[s + 1] = cx; oy[s + 1] = cy; oz[s + 1] = cz;
        }
    }
}

// ---------------------------------------------------------------------------
// Kernel 2: ball query. One warp per center; 128 points per outer step
// (4 independent ballots) to batch load latency; ascending-index compaction
// with early exit at K hits; pads with first hit (0 if none).
// ---------------------------------------------------------------------------
__global__ __launch_bounds__(256) void bq_kernel(
    const float* __restrict__ coords, const float* __restrict__ centers)
{
    const int gw   = (blockIdx.x * blockDim.x + threadIdx.x) >> 5;
    const int lane = threadIdx.x & 31;
    if (gw >= BATCH * M) return;
    const int b = gw >> 11, m = gw & (M - 1);

    const float* X = coords + (size_t)b * 3 * NPTS;
    const float* Y = X + NPTS;
    const float* Z = X + 2 * NPTS;
    const float* C = centers + (size_t)b * 3 * M;
    const float cx = C[m], cy = C[M + m], cz = C[2 * M + m];

    const int base = gw * KNN;
    int cnt = 0, firstn = 0;

    for (int c0 = 0; c0 < NPTS && cnt < KNN; c0 += 128) {
        unsigned msk[4];
#pragma unroll
        for (int u = 0; u < 4; u++) {
            const int n = c0 + u * 32 + lane;
            float dx = X[n] - cx, dy = Y[n] - cy, dz = Z[n] - cz;
            float d2 = fmaf(dz, dz, fmaf(dy, dy, dx * dx));
            msk[u] = __ballot_sync(0xffffffffu, d2 < R2);
        }
#pragma unroll
        for (int u = 0; u < 4; u++) {
            if (cnt < KNN) {
                const unsigned mask = msk[u];
                const int n = c0 + u * 32 + lane;
                if (cnt == 0 && mask) firstn = c0 + u * 32 + __ffs(mask) - 1;
                bool hit = (mask >> lane) & 1u;
                int pos = cnt + __popc(mask & ((1u << lane) - 1u));
                if (hit && pos < KNN) g_idx[base + pos] = n;
                cnt += __popc(mask);
            }
        }
    }
    for (int j = cnt + lane; j < KNN; j += 32) g_idx[base + j] = firstn;
}

// ---------------------------------------------------------------------------
// Kernel 2.5: one-time weight transpose into global scratch (smem images).
// ---------------------------------------------------------------------------
__global__ void prep_kernel(
    const float* __restrict__ W1, const float* __restrict__ B1,
    const float* __restrict__ W2, const float* __restrict__ B2,
    const float* __restrict__ W3, const float* __restrict__ B3)
{
    int i = blockIdx.x * blockDim.x + threadIdx.x;
    if (i >= WTOT) return;
    float v;
    if (i < 2240)       { int j = i;         int c = j >> 6, o = j & 63;  v = W1[o * 35 + c]; }
    else if (i < 6336)  { int j = i - 2240;  int c = j >> 6, o = j & 63;  v = W2[o * 64 + c]; }
    else if (i < 14528) { int j = i - 6336;  int c = j >> 7, o = j & 127; v = W3[o * 64 + c]; }
    else if (i < 14592) v = B1[i - 14528];
    else if (i < 14656) v = B2[i - 14592];
    else                v = B3[i - 14656];
    g_w[i] = v;
}

// ---------------------------------------------------------------------------
// Kernel 3a: gather + layer1 (35->64), packed f32x2 accumulators.
// Two 32-output passes (acc[16]) to cut live registers -> 3 blocks/SM.
// ---------------------------------------------------------------------------
__global__ __launch_bounds__(256, 3) void mlp1_kernel(
    const float* __restrict__ coords, const float* __restrict__ feats,
    const float* __restrict__ centers)
{
    extern __shared__ float sm[];           // w1t (2240) + b1 (64)
    const int tid = threadIdx.x;
    for (int i = tid; i < 560; i += 256)
        ((float4*)sm)[i] = ((const float4*)g_w)[i];
    if (tid < 64) sm[2240 + tid] = g_w[14528 + tid];
    __syncthreads();

    const int wid = tid >> 5, lane = tid & 31;
    const int gw = blockIdx.x * 8 + wid;
    const int b = gw >> 11, m = gw & (M - 1);

    const int idx = g_idx[gw * KNN + lane];
    const float* X = coords + (size_t)b * 3 * NPTS;
    const float* F = feats + (size_t)b * CF * NPTS;
    const float* C = centers + (size_t)b * 3 * M;

    float in[35];
    in[0] = X[idx]            - C[m];
    in[1] = X[NPTS + idx]     - C[M + m];
    in[2] = X[2 * NPTS + idx] - C[2 * M + m];
#pragma unroll
    for (int c = 0; c < CF; c++) in[3 + c] = F[c * NPTS + idx];

    const ull* bp = (const ull*)(sm + 2240);
    ull* H = g_h1 + (size_t)gw * 1024 + lane;

#pragma unroll
    for (int half = 0; half < 2; half++) {
        ull acc[16];
#pragma unroll
        for (int i = 0; i < 16; i++) acc[i] = bp[half * 16 + i];
#pragma unroll
        for (int c = 0; c < 35; c++) {
            const ull xx = f2pack(in[c], in[c]);
            const ulonglong2* pw = (const ulonglong2*)(sm + c * 64 + half * 32);
#pragma unroll
            for (int i = 0; i < 8; i++) {
                const ulonglong2 w = pw[i];
                F2FMA(acc[2 * i],     w.x, xx, acc[2 * i]);
                F2FMA(acc[2 * i + 1], w.y, xx, acc[2 * i + 1]);
            }
        }
#pragma unroll
        for (int i = 0; i < 16; i++) {
            float a, c2; f2unpack(acc[i], a, c2);
            H[(half * 16 + i) * 32] = f2pack(fmaxf(a, 0.f), fmaxf(c2, 0.f));
        }
    }
}

// ---------------------------------------------------------------------------
// Kernel 3b: layer2 + layer3 + maxpool, packed f32x2.
// ---------------------------------------------------------------------------
__global__ __launch_bounds__(256, 2) void mlp2_kernel(float* __restrict__ out)
{
    extern __shared__ float sm[];
    const int tid = threadIdx.x;
    for (int i = tid; i < 3136; i += 256)
        ((float4*)sm)[i] = ((const float4*)(g_w + 2240))[i];
    __syncthreads();

    float* w2t = sm;                 // [64][64]
    float* w3t = sm + 4096;          // [64][128]
    const ull* bias2 = (const ull*)(sm + 12352);
    const ull* bias3 = (const ull*)(sm + 12416);

    const int wid = tid >> 5, lane = tid & 31;
    const int gw = blockIdx.x * 8 + wid;
    const int b = gw >> 11, m = gw & (M - 1);

    const ull* H = g_h1 + (size_t)gw * 1024 + lane;

    ull acc[32];
#pragma unroll
    for (int i = 0; i < 32; i++) acc[i] = bias2[i];

    for (int blk = 0; blk < 4; blk++) {
        ull h1p[8];
#pragma unroll
        for (int t = 0; t < 8; t++) h1p[t] = H[(blk * 8 + t) * 32];
#pragma unroll
        for (int t = 0; t < 8; t++) {
            float x0, x1; f2unpack(h1p[t], x0, x1);
            const ull xx0 = f2pack(x0, x0), xx1 = f2pack(x1, x1);
            const int c = blk * 16 + 2 * t;
            const ulonglong2* pw0 = (const ulonglong2*)(w2t + c * 64);
            const ulonglong2* pw1 = (const ulonglong2*)(w2t + (c + 1) * 64);
#pragma unroll
            for (int i = 0; i < 16; i++) {
                const ulonglong2 w = pw0[i];
                F2FMA(acc[2 * i],     w.x, xx0, acc[2 * i]);
                F2FMA(acc[2 * i + 1], w.y, xx0, acc[2 * i + 1]);
            }
#pragma unroll
            for (int i = 0; i < 16; i++) {
                const ulonglong2 w = pw1[i];
                F2FMA(acc[2 * i],     w.x, xx1, acc[2 * i]);
                F2FMA(acc[2 * i + 1], w.y, xx1, acc[2 * i + 1]);
            }
        }
    }

    float h2[64];
#pragma unroll
    for (int i = 0; i < 32; i++) {
        float a, c2; f2unpack(acc[i], a, c2);
        h2[2 * i] = fmaxf(a, 0.f); h2[2 * i + 1] = fmaxf(c2, 0.f);
    }

    float* O = out + (size_t)b * 128 * M + m;
    for (int q = 0; q < 4; q++) {
        ull a3[16];
#pragma unroll
        for (int i = 0; i < 16; i++) a3[i] = bias3[q * 16 + i];
#pragma unroll
        for (int c = 0; c < 64; c++) {
            const ull xx = f2pack(h2[c], h2[c]);
            const ulonglong2* pw = (const ulonglong2*)(w3t + c * 128 + q * 32);
#pragma unroll
            for (int i = 0; i < 8; i++) {
                const ulonglong2 w = pw[i];
                F2FMA(a3[2 * i],     w.x, xx, a3[2 * i]);
                F2FMA(a3[2 * i + 1], w.y, xx, a3[2 * i + 1]);
            }
        }
#pragma unroll
        for (int i = 0; i < 16; i++) {
            float u, v; f2unpack(a3[i], u, v);
            u = fmaxf(u, 0.f); v = fmaxf(v, 0.f);
#pragma unroll
            for (int off = 16; off; off >>= 1) {
                u = fmaxf(u, __shfl_xor_sync(0xffffffffu, u, off));
                v = fmaxf(v, __shfl_xor_sync(0xffffffffu, v, off));
            }
            if (lane == 0) {
                O[(q * 32 + 2 * i) * M]     = u;
                O[(q * 32 + 2 * i + 1) * M] = v;
            }
        }
    }
}

// ---------------------------------------------------------------------------
extern "C" void kernel_launch(void* const* d_in, const int* in_sizes, int n_in,
                              void* d_out, int out_size)
{
    const float* feats  = (const float*)d_in[0];
    const float* coords = (const float*)d_in[1];
    const float* W1 = (const float*)d_in[2];
    const float* B1 = (const float*)d_in[3];
    const float* W2 = (const float*)d_in[4];
    const float* B2 = (const float*)d_in[5];
    const float* W3 = (const float*)d_in[6];
    const float* B3 = (const float*)d_in[7];

    float* out     = (float*)d_out;
    float* centers = out + (size_t)BATCH * 128 * M;

    sort_kernel<<<BATCH, 1024>>>(coords);
    prep_kernel<<<(WTOT + 255) / 256, 256>>>(W1, B1, W2, B2, W3, B3);

    fps_kernel<<<BATCH, 1024>>>(coords, centers);

    bq_kernel<<<(BATCH * M) / 8, 256>>>(coords, centers);

    const int SMEM1 = 2304 * 4;
    const int SMEM2 = 12544 * 4;
    cudaFuncSetAttribute(mlp1_kernel, cudaFuncAttributeMaxDynamicSharedMemorySize, SMEM1);
    cudaFuncSetAttribute(mlp2_kernel, cudaFuncAttributeMaxDynamicSharedMemorySize, SMEM2);
    mlp1_kernel<<<(BATCH * M) / 8, 256, SMEM1>>>(coords, feats, centers);
    mlp2_kernel<<<(BATCH * M) / 8, 256, SMEM2>>>(out);
}

// round 12
// speedup vs baseline: 1.3642x; 1.3642x over previous
#include <cuda_runtime.h>

#define NPTS   8192
#define BATCH  4
#define M      2048
#define KNN    32
#define CF     32
#define R2     0.04f

typedef unsigned long long ull;

// scratch (no allocations allowed)
__device__ int   g_idx[BATCH * M * KNN];
#define WTOT (35*64 + 64*64 + 64*128 + 64 + 64 + 128)   // 14784
__device__ float g_w[WTOT];
// h1 staging: [gw (8192)][channel-pair (32)][neighbor lane (32)], packed f32x2
__device__ ull   g_h1[(size_t)BATCH * M * 32 * 32];
// spatially sorted points (Morton-cell order) + original indices
__device__ float g_sx[BATCH * NPTS], g_sy[BATCH * NPTS], g_sz[BATCH * NPTS];
__device__ int   g_si[BATCH * NPTS];

// ---- packed f32x2 helpers (bit-identical IEEE f32 per lane) ----------------
__device__ __forceinline__ ull f2pack(float a, float b) {
    ull r; asm("mov.b64 %0, {%1,%2};" : "=l"(r) : "f"(a), "f"(b)); return r;
}
__device__ __forceinline__ void f2unpack(ull v, float& a, float& b) {
    asm("mov.b64 {%0,%1}, %2;" : "=f"(a), "=f"(b) : "l"(v));
}
#define F2ADD(d, a, b)    asm("add.rn.f32x2 %0, %1, %2;"     : "=l"(d) : "l"(a), "l"(b))
#define F2MUL(d, a, b)    asm("mul.rn.f32x2 %0, %1, %2;"     : "=l"(d) : "l"(a), "l"(b))
#define F2FMA(d, a, b, c) asm("fma.rn.f32x2 %0, %1, %2, %3;" : "=l"(d) : "l"(a), "l"(b), "l"(c))

__device__ __forceinline__ unsigned redux_max_u32(unsigned v) {
    unsigned r; asm("redux.sync.max.u32 %0, %1, 0xffffffff;" : "=r"(r) : "r"(v)); return r;
}
__device__ __forceinline__ unsigned redux_min_u32(unsigned v) {
    unsigned r; asm("redux.sync.min.u32 %0, %1, 0xffffffff;" : "=r"(r) : "r"(v)); return r;
}

__device__ __forceinline__ unsigned spread3_4(unsigned v) {  // 4 bits -> every 3rd
    unsigned r = (v & 1u);
    r |= (v & 2u) << 2;
    r |= (v & 4u) << 4;
    r |= (v & 8u) << 6;
    return r;
}

// ---------------------------------------------------------------------------
// Kernel 0: spatial bucket sort (blocks 0..BATCH-1) + weight-transpose prep
// (blocks BATCH..). Fusing prep here saves one launch.
// ---------------------------------------------------------------------------
__global__ __launch_bounds__(1024, 1) void sort_kernel(
    const float* __restrict__ coords,
    const float* __restrict__ W1, const float* __restrict__ B1,
    const float* __restrict__ W2, const float* __restrict__ B2,
    const float* __restrict__ W3, const float* __restrict__ B3)
{
    __shared__ int cnt[4096];
    __shared__ int ss[1024];
    const int tid = threadIdx.x;

    if (blockIdx.x >= BATCH) {               // prep portion
        int i = (blockIdx.x - BATCH) * 1024 + tid;
        if (i < WTOT) {
            float v;
            if (i < 2240)       { int j = i;         int c = j >> 6, o = j & 63;  v = W1[o * 35 + c]; }
            else if (i < 6336)  { int j = i - 2240;  int c = j >> 6, o = j & 63;  v = W2[o * 64 + c]; }
            else if (i < 14528) { int j = i - 6336;  int c = j >> 7, o = j & 127; v = W3[o * 64 + c]; }
            else if (i < 14592) v = B1[i - 14528];
            else if (i < 14656) v = B2[i - 14592];
            else                v = B3[i - 14656];
            g_w[i] = v;
        }
        return;
    }

    const int b = blockIdx.x;
    const float* X = coords + (size_t)b * 3 * NPTS;
    const float* Y = X + NPTS;
    const float* Z = X + 2 * NPTS;

    for (int i = tid; i < 4096; i += 1024) cnt[i] = 0;
    __syncthreads();

    int cell8[8];
#pragma unroll
    for (int i = 0; i < 8; i++) {
        int n = tid + i * 1024;
        int cx = min(15, (int)(X[n] * 16.0f));
        int cy = min(15, (int)(Y[n] * 16.0f));
        int cz = min(15, (int)(Z[n] * 16.0f));
        int cell = spread3_4(cx) | (spread3_4(cy) << 1) | (spread3_4(cz) << 2);
        cell8[i] = cell;
        atomicAdd(&cnt[cell], 1);
    }
    __syncthreads();

    int l0 = cnt[4 * tid], l1 = cnt[4 * tid + 1], l2 = cnt[4 * tid + 2], l3 = cnt[4 * tid + 3];
    int local = l0 + l1 + l2 + l3;
    ss[tid] = local;
    __syncthreads();
    for (int off = 1; off < 1024; off <<= 1) {
        int v = (tid >= off) ? ss[tid - off] : 0;
        __syncthreads();
        ss[tid] += v;
        __syncthreads();
    }
    int ex = ss[tid] - local;
    cnt[4 * tid]     = ex;
    cnt[4 * tid + 1] = ex + l0;
    cnt[4 * tid + 2] = ex + l0 + l1;
    cnt[4 * tid + 3] = ex + l0 + l1 + l2;
    __syncthreads();

#pragma unroll
    for (int i = 0; i < 8; i++) {
        int n = tid + i * 1024;
        int pos = atomicAdd(&cnt[cell8[i]], 1);
        g_sx[b * NPTS + pos] = X[n];
        g_sy[b * NPTS + pos] = Y[n];
        g_sz[b * NPTS + pos] = Z[n];
        g_si[b * NPTS + pos] = n;
    }
}

// ---------------------------------------------------------------------------
// Kernel 1: furthest point sampling with exact THREAD-level spatial pruning
// (round-9 proven config: 512 threads, 16 spatially-contiguous pts/thread,
// depth-4 max tree, predicated index scan, STS->BAR->LDS->redux stage-2).
// New: all coords staged in dynamic smem so the per-iteration centroid fetch
// is 3 broadcast LDS instead of 3 LDG. Staging STS are ordered before the
// first smem coord read by the iteration-0 __syncthreads.
// ---------------------------------------------------------------------------
__global__ __launch_bounds__(512, 1) void fps_kernel(
    const float* __restrict__ coords, float* __restrict__ centers)
{
    extern __shared__ float smc[];           // [3*NPTS] coords + skey tail
    const int b = blockIdx.x, tid = threadIdx.x;
    const int wid = tid >> 5, lane = tid & 31;
    const float* X = coords + (size_t)b * 3 * NPTS;
    const float* Y = X + NPTS;
    const float* Z = X + 2 * NPTS;
    const float* SX = g_sx + b * NPTS;
    const float* SY = g_sy + b * NPTS;
    const float* SZ = g_sz + b * NPTS;
    const int*   SI = g_si + b * NPTS;

    // stage all coords into smem (coalesced float4 sweep)
    for (int i = tid; i < (3 * NPTS) / 4; i += 512)
        ((float4*)smc)[i] = ((const float4*)X)[i];
    const float* smx = smc;
    const float* smy = smc + NPTS;
    const float* smz = smc + 2 * NPTS;
    ull* skey = (ull*)(smc + 3 * NPTS);      // [2][16]

    ull px2[8], py2[8], pz2[8];
    int oi[16];
    float dl[16];
    float bxmin = 1e30f, bxmax = -1e30f, bymin = 1e30f, bymax = -1e30f,
          bzmin = 1e30f, bzmax = -1e30f;
    const int base = tid * 16;
#pragma unroll
    for (int j = 0; j < 8; j++) {
        float x0 = SX[base + 2*j], x1 = SX[base + 2*j + 1];
        float y0 = SY[base + 2*j], y1 = SY[base + 2*j + 1];
        float z0 = SZ[base + 2*j], z1 = SZ[base + 2*j + 1];
        px2[j] = f2pack(x0, x1); py2[j] = f2pack(y0, y1); pz2[j] = f2pack(z0, z1);
        oi[2*j] = SI[base + 2*j]; oi[2*j + 1] = SI[base + 2*j + 1];
        dl[2*j] = 1e30f; dl[2*j + 1] = 1e30f;
        bxmin = fminf(bxmin, fminf(x0, x1)); bxmax = fmaxf(bxmax, fmaxf(x0, x1));
        bymin = fminf(bymin, fminf(y0, y1)); bymax = fmaxf(bymax, fmaxf(y0, y1));
        bzmin = fminf(bzmin, fminf(z0, z1)); bzmax = fmaxf(bzmax, fmaxf(z0, z1));
    }

    float* ox = centers + (size_t)b * 3 * M;
    float* oy = ox + M;
    float* oz = ox + 2 * M;

    float cx = __ldg(X), cy = __ldg(Y), cz = __ldg(Z);
    if (tid == 0) { ox[0] = cx; oy[0] = cy; oz[0] = cz; }

    float bm = 1e30f;            // cached thread-best distance (max of dl)
    int   bi = 0x7fffffff;       // cached thread-best original index

    for (int s = 0; s < M; s++) {
        // conservative lower bound on d2(c, any owned point)
        float tx = fmaxf(fmaxf(bxmin - cx, cx - bxmax), 0.0f);
        float ty = fmaxf(fmaxf(bymin - cy, cy - bymax), 0.0f);
        float tz = fmaxf(fmaxf(bzmin - cz, cz - bzmax), 0.0f);
        float lb2 = fmaf(tz, tz, fmaf(ty, ty, tx * tx));

        if (!(lb2 * 0.999f > bm)) {          // active: some dl may change
            const ull ncx = f2pack(-cx, -cx);
            const ull ncy = f2pack(-cy, -cy);
            const ull ncz = f2pack(-cz, -cz);
            // 1) distance updates (independent per pair)
#pragma unroll
            for (int j = 0; j < 8; j++) {
                ull dx, dy, dz, t;
                F2ADD(dx, px2[j], ncx);
                F2ADD(dy, py2[j], ncy);
                F2ADD(dz, pz2[j], ncz);
                F2MUL(t, dx, dx);
                F2FMA(t, dy, dy, t);
                F2FMA(t, dz, dz, t);
                float t0, t1; f2unpack(t, t0, t1);
                dl[2*j]     = fminf(dl[2*j],     t0);
                dl[2*j + 1] = fminf(dl[2*j + 1], t1);
            }
            // 2) max tree (depth 4)
            float m0 = fmaxf(dl[0],  dl[1]),  m1 = fmaxf(dl[2],  dl[3]);
            float m2 = fmaxf(dl[4],  dl[5]),  m3 = fmaxf(dl[6],  dl[7]);
            float m4 = fmaxf(dl[8],  dl[9]),  m5 = fmaxf(dl[10], dl[11]);
            float m6 = fmaxf(dl[12], dl[13]), m7 = fmaxf(dl[14], dl[15]);
            m0 = fmaxf(m0, m1); m2 = fmaxf(m2, m3);
            m4 = fmaxf(m4, m5); m6 = fmaxf(m6, m7);
            m0 = fmaxf(m0, m2); m4 = fmaxf(m4, m6);
            bm = fmaxf(m0, m4);
            // 3) lowest original index among dl==bm (independent predicated ops)
            int mi = 0x7fffffff;
#pragma unroll
            for (int k = 0; k < 16; k++)
                if (dl[k] == bm) mi = min(mi, oi[k]);
            bi = mi;
        }

        // stage 1: max distance bits, then min original index among ties
        unsigned mb = __float_as_uint(bm);          // bm >= 0 -> monotone bits
        unsigned wm = redux_max_u32(mb);
        unsigned ci = (mb == wm) ? (unsigned)bi : 0x7fffffffu;
        unsigned wi = redux_min_u32(ci);
        if (lane == 0) skey[(s & 1) * 16 + wid] = ((ull)wm << 32) | wi;
        __syncthreads();

        // stage 2: every warp reduces the 16 warp keys redundantly
        ull k = skey[(s & 1) * 16 + (lane & 15)];
        unsigned v  = (unsigned)(k >> 32);
        unsigned ii = (unsigned)k;
        unsigned gm = redux_max_u32(v);
        unsigned c2 = (v == gm) ? ii : 0x7fffffffu;
        unsigned gi = redux_min_u32(c2);

        cx = smx[gi]; cy = smy[gi]; cz = smz[gi];   // broadcast LDS
        if (tid == 0 && s + 1 < M) {
            ox[s + 1] = cx; oy[s + 1] = cy; oz[s + 1] = cz;
        }
    }
}

// ---------------------------------------------------------------------------
// Kernel 2: ball query. One warp per center, 128-thread blocks for tail
// balance; 128 points per outer step (4 independent ballots); ascending-
// index compaction with early exit at K hits; pads with first hit (0 if none).
// ---------------------------------------------------------------------------
__global__ __launch_bounds__(128) void bq_kernel(
    const float* __restrict__ coords, const float* __restrict__ centers)
{
    const int gw   = (blockIdx.x * blockDim.x + threadIdx.x) >> 5;
    const int lane = threadIdx.x & 31;
    if (gw >= BATCH * M) return;
    const int b = gw >> 11, m = gw & (M - 1);

    const float* X = coords + (size_t)b * 3 * NPTS;
    const float* Y = X + NPTS;
    const float* Z = X + 2 * NPTS;
    const float* C = centers + (size_t)b * 3 * M;
    const float cx = C[m], cy = C[M + m], cz = C[2 * M + m];

    const int base = gw * KNN;
    int cnt = 0, firstn = 0;

    for (int c0 = 0; c0 < NPTS && cnt < KNN; c0 += 128) {
        unsigned msk[4];
#pragma unroll
        for (int u = 0; u < 4; u++) {
            const int n = c0 + u * 32 + lane;
            float dx = X[n] - cx, dy = Y[n] - cy, dz = Z[n] - cz;
            float d2 = fmaf(dz, dz, fmaf(dy, dy, dx * dx));
            msk[u] = __ballot_sync(0xffffffffu, d2 < R2);
        }
#pragma unroll
        for (int u = 0; u < 4; u++) {
            if (cnt < KNN) {
                const unsigned mask = msk[u];
                const int n = c0 + u * 32 + lane;
                if (cnt == 0 && mask) firstn = c0 + u * 32 + __ffs(mask) - 1;
                bool hit = (mask >> lane) & 1u;
                int pos = cnt + __popc(mask & ((1u << lane) - 1u));
                if (hit && pos < KNN) g_idx[base + pos] = n;
                cnt += __popc(mask);
            }
        }
    }
    for (int j = cnt + lane; j < KNN; j += 32) g_idx[base + j] = firstn;
}

// ---------------------------------------------------------------------------
// Kernel 3a: gather + layer1 (35->64), packed f32x2 accumulators.
// Two 32-output passes (acc[16]) to cut live registers -> 3 blocks/SM.
// ---------------------------------------------------------------------------
__global__ __launch_bounds__(256, 3) void mlp1_kernel(
    const float* __restrict__ coords, const float* __restrict__ feats,
    const float* __restrict__ centers)
{
    extern __shared__ float sm[];           // w1t (2240) + b1 (64)
    const int tid = threadIdx.x;
    for (int i = tid; i < 560; i += 256)
        ((float4*)sm)[i] = ((const float4*)g_w)[i];
    if (tid < 64) sm[2240 + tid] = g_w[14528 + tid];
    __syncthreads();

    const int wid = tid >> 5, lane = tid & 31;
    const int gw = blockIdx.x * 8 + wid;
    const int b = gw >> 11, m = gw & (M - 1);

    const int idx = g_idx[gw * KNN + lane];
    const float* X = coords + (size_t)b * 3 * NPTS;
    const float* F = feats + (size_t)b * CF * NPTS;
    const float* C = centers + (size_t)b * 3 * M;

    float in[35];
    in[0] = X[idx]            - C[m];
    in[1] = X[NPTS + idx]     - C[M + m];
    in[2] = X[2 * NPTS + idx] - C[2 * M + m];
#pragma unroll
    for (int c = 0; c < CF; c++) in[3 + c] = F[c * NPTS + idx];

    const ull* bp = (const ull*)(sm + 2240);
    ull* H = g_h1 + (size_t)gw * 1024 + lane;

#pragma unroll
    for (int half = 0; half < 2; half++) {
        ull acc[16];
#pragma unroll
        for (int i = 0; i < 16; i++) acc[i] = bp[half * 16 + i];
#pragma unroll
        for (int c = 0; c < 35; c++) {
            const ull xx = f2pack(in[c], in[c]);
            const ulonglong2* pw = (const ulonglong2*)(sm + c * 64 + half * 32);
#pragma unroll
            for (int i = 0; i < 8; i++) {
                const ulonglong2 w = pw[i];
                F2FMA(acc[2 * i],     w.x, xx, acc[2 * i]);
                F2FMA(acc[2 * i + 1], w.y, xx, acc[2 * i + 1]);
            }
        }
#pragma unroll
        for (int i = 0; i < 16; i++) {
            float a, c2; f2unpack(acc[i], a, c2);
            H[(half * 16 + i) * 32] = f2pack(fmaxf(a, 0.f), fmaxf(c2, 0.f));
        }
    }
}

// ---------------------------------------------------------------------------
// Kernel 3b: layer2 + layer3 + maxpool, packed f32x2.
// ---------------------------------------------------------------------------
__global__ __launch_bounds__(256, 2) void mlp2_kernel(float* __restrict__ out)
{
    extern __shared__ float sm[];
    const int tid = threadIdx.x;
    for (int i = tid; i < 3136; i += 256)
        ((float4*)sm)[i] = ((const float4*)(g_w + 2240))[i];
    __syncthreads();

    float* w2t = sm;                 // [64][64]
    float* w3t = sm + 4096;          // [64][128]
    const ull* bias2 = (const ull*)(sm + 12352);
    const ull* bias3 = (const ull*)(sm + 12416);

    const int wid = tid >> 5, lane = tid & 31;
    const int gw = blockIdx.x * 8 + wid;
    const int b = gw >> 11, m = gw & (M - 1);

    const ull* H = g_h1 + (size_t)gw * 1024 + lane;

    ull acc[32];
#pragma unroll
    for (int i = 0; i < 32; i++) acc[i] = bias2[i];

    for (int blk = 0; blk < 4; blk++) {
        ull h1p[8];
#pragma unroll
        for (int t = 0; t < 8; t++) h1p[t] = H[(blk * 8 + t) * 32];
#pragma unroll
        for (int t = 0; t < 8; t++) {
            float x0, x1; f2unpack(h1p[t], x0, x1);
            const ull xx0 = f2pack(x0, x0), xx1 = f2pack(x1, x1);
            const int c = blk * 16 + 2 * t;
            const ulonglong2* pw0 = (const ulonglong2*)(w2t + c * 64);
            const ulonglong2* pw1 = (const ulonglong2*)(w2t + (c + 1) * 64);
#pragma unroll
            for (int i = 0; i < 16; i++) {
                const ulonglong2 w = pw0[i];
                F2FMA(acc[2 * i],     w.x, xx0, acc[2 * i]);
                F2FMA(acc[2 * i + 1], w.y, xx0, acc[2 * i + 1]);
            }
#pragma unroll
            for (int i = 0; i < 16; i++) {
                const ulonglong2 w = pw1[i];
                F2FMA(acc[2 * i],     w.x, xx1, acc[2 * i]);
                F2FMA(acc[2 * i + 1], w.y, xx1, acc[2 * i + 1]);
            }
        }
    }

    float h2[64];
#pragma unroll
    for (int i = 0; i < 32; i++) {
        float a, c2; f2unpack(acc[i], a, c2);
        h2[2 * i] = fmaxf(a, 0.f); h2[2 * i + 1] = fmaxf(c2, 0.f);
    }

    float* O = out + (size_t)b * 128 * M + m;
    for (int q = 0; q < 4; q++) {
        ull a3[16];
#pragma unroll
        for (int i = 0; i < 16; i++) a3[i] = bias3[q * 16 + i];
#pragma unroll
        for (int c = 0; c < 64; c++) {
            const ull xx = f2pack(h2[c], h2[c]);
            const ulonglong2* pw = (const ulonglong2*)(w3t + c * 128 + q * 32);
#pragma unroll
            for (int i = 0; i < 8; i++) {
                const ulonglong2 w = pw[i];
                F2FMA(a3[2 * i],     w.x, xx, a3[2 * i]);
                F2FMA(a3[2 * i + 1], w.y, xx, a3[2 * i + 1]);
            }
        }
#pragma unroll
        for (int i = 0; i < 16; i++) {
            float u, v; f2unpack(a3[i], u, v);
            u = fmaxf(u, 0.f); v = fmaxf(v, 0.f);
#pragma unroll
            for (int off = 16; off; off >>= 1) {
                u = fmaxf(u, __shfl_xor_sync(0xffffffffu, u, off));
                v = fmaxf(v, __shfl_xor_sync(0xffffffffu, v, off));
            }
            if (lane == 0) {
                O[(q * 32 + 2 * i) * M]     = u;
                O[(q * 32 + 2 * i + 1) * M] = v;
            }
        }
    }
}

// ---------------------------------------------------------------------------
extern "C" void kernel_launch(void* const* d_in, const int* in_sizes, int n_in,
                              void* d_out, int out_size)
{
    const float* feats  = (const float*)d_in[0];
    const float* coords = (const float*)d_in[1];
    const float* W1 = (const float*)d_in[2];
    const float* B1 = (const float*)d_in[3];
    const float* W2 = (const float*)d_in[4];
    const float* B2 = (const float*)d_in[5];
    const float* W3 = (const float*)d_in[6];
    const float* B3 = (const float*)d_in[7];

    float* out     = (float*)d_out;
    float* centers = out + (size_t)BATCH * 128 * M;

    // sort (blocks 0..3) + prep (blocks 4..18) fused
    sort_kernel<<<BATCH + (WTOT + 1023) / 1024, 1024>>>(
        coords, W1, B1, W2, B2, W3, B3);

    const int SMEMF = (3 * NPTS) * 4 + 2 * 16 * 8;   // coords + skey
    cudaFuncSetAttribute(fps_kernel, cudaFuncAttributeMaxDynamicSharedMemorySize, SMEMF);
    fps_kernel<<<BATCH, 512, SMEMF>>>(coords, centers);

    bq_kernel<<<(BATCH * M) / 4, 128>>>(coords, centers);

    const int SMEM1 = 2304 * 4;
    const int SMEM2 = 12544 * 4;
    cudaFuncSetAttribute(mlp1_kernel, cudaFuncAttributeMaxDynamicSharedMemorySize, SMEM1);
    cudaFuncSetAttribute(mlp2_kernel, cudaFuncAttributeMaxDynamicSharedMemorySize, SMEM2);
    mlp1_kernel<<<(BATCH * M) / 8, 256, SMEM1>>>(coords, feats, centers);
    mlp2_kernel<<<(BATCH * M) / 8, 256, SMEM2>>>(out);
}

// round 14
// speedup vs baseline: 1.4025x; 1.0281x over previous
#include <cuda_runtime.h>

#define NPTS   8192
#define BATCH  4
#define M      2048
#define KNN    32
#define CF     32
#define R2     0.04f

typedef unsigned long long ull;

// scratch (no allocations allowed)
__device__ int   g_idx[BATCH * M * KNN];
#define WTOT (35*64 + 64*64 + 64*128 + 64 + 64 + 128)   // 14784
__device__ float g_w[WTOT];
// per-point layer-1 pre-activation: prept[p] = W1c*p + W1f*f(p) + b1
// layout: [b*NPTS + n (32768)][channel-pair (32)] packed f32x2, 256B/point
__device__ __align__(16) ull g_pp[(size_t)BATCH * NPTS * 32];
// spatially sorted points (Morton-cell order) + original indices
__device__ float g_sx[BATCH * NPTS], g_sy[BATCH * NPTS], g_sz[BATCH * NPTS];
__device__ int   g_si[BATCH * NPTS];

// ---- packed f32x2 helpers (bit-identical IEEE f32 per lane) ----------------
__device__ __forceinline__ ull f2pack(float a, float b) {
    ull r; asm("mov.b64 %0, {%1,%2};" : "=l"(r) : "f"(a), "f"(b)); return r;
}
__device__ __forceinline__ void f2unpack(ull v, float& a, float& b) {
    asm("mov.b64 {%0,%1}, %2;" : "=f"(a), "=f"(b) : "l"(v));
}
#define F2ADD(d, a, b)    asm("add.rn.f32x2 %0, %1, %2;"     : "=l"(d) : "l"(a), "l"(b))
#define F2MUL(d, a, b)    asm("mul.rn.f32x2 %0, %1, %2;"     : "=l"(d) : "l"(a), "l"(b))
#define F2FMA(d, a, b, c) asm("fma.rn.f32x2 %0, %1, %2, %3;" : "=l"(d) : "l"(a), "l"(b), "l"(c))

__device__ __forceinline__ unsigned redux_max_u32(unsigned v) {
    unsigned r; asm("redux.sync.max.u32 %0, %1, 0xffffffff;" : "=r"(r) : "r"(v)); return r;
}
__device__ __forceinline__ unsigned redux_min_u32(unsigned v) {
    unsigned r; asm("redux.sync.min.u32 %0, %1, 0xffffffff;" : "=r"(r) : "r"(v)); return r;
}

__device__ __forceinline__ unsigned spread3_4(unsigned v) {  // 4 bits -> every 3rd
    unsigned r = (v & 1u);
    r |= (v & 2u) << 2;
    r |= (v & 4u) << 4;
    r |= (v & 8u) << 6;
    return r;
}

// ---------------------------------------------------------------------------
// Kernel 0: spatial bucket sort (blocks 0..BATCH-1) + weight-transpose prep
// (blocks BATCH..).
// ---------------------------------------------------------------------------
__global__ __launch_bounds__(1024, 1) void sort_kernel(
    const float* __restrict__ coords,
    const float* __restrict__ W1, const float* __restrict__ B1,
    const float* __restrict__ W2, const float* __restrict__ B2,
    const float* __restrict__ W3, const float* __restrict__ B3)
{
    __shared__ int cnt[4096];
    __shared__ int ss[1024];
    const int tid = threadIdx.x;

    if (blockIdx.x >= BATCH) {               // prep portion
        int i = (blockIdx.x - BATCH) * 1024 + tid;
        if (i < WTOT) {
            float v;
            if (i < 2240)       { int j = i;         int c = j >> 6, o = j & 63;  v = W1[o * 35 + c]; }
            else if (i < 6336)  { int j = i - 2240;  int c = j >> 6, o = j & 63;  v = W2[o * 64 + c]; }
            else if (i < 14528) { int j = i - 6336;  int c = j >> 7, o = j & 127; v = W3[o * 64 + c]; }
            else if (i < 14592) v = B1[i - 14528];
            else if (i < 14656) v = B2[i - 14592];
            else                v = B3[i - 14656];
            g_w[i] = v;
        }
        return;
    }

    const int b = blockIdx.x;
    const float* X = coords + (size_t)b * 3 * NPTS;
    const float* Y = X + NPTS;
    const float* Z = X + 2 * NPTS;

    for (int i = tid; i < 4096; i += 1024) cnt[i] = 0;
    __syncthreads();

    int cell8[8];
#pragma unroll
    for (int i = 0; i < 8; i++) {
        int n = tid + i * 1024;
        int cx = min(15, (int)(X[n] * 16.0f));
        int cy = min(15, (int)(Y[n] * 16.0f));
        int cz = min(15, (int)(Z[n] * 16.0f));
        int cell = spread3_4(cx) | (spread3_4(cy) << 1) | (spread3_4(cz) << 2);
        cell8[i] = cell;
        atomicAdd(&cnt[cell], 1);
    }
    __syncthreads();

    int l0 = cnt[4 * tid], l1 = cnt[4 * tid + 1], l2 = cnt[4 * tid + 2], l3 = cnt[4 * tid + 3];
    int local = l0 + l1 + l2 + l3;
    ss[tid] = local;
    __syncthreads();
    for (int off = 1; off < 1024; off <<= 1) {
        int v = (tid >= off) ? ss[tid - off] : 0;
        __syncthreads();
        ss[tid] += v;
        __syncthreads();
    }
    int ex = ss[tid] - local;
    cnt[4 * tid]     = ex;
    cnt[4 * tid + 1] = ex + l0;
    cnt[4 * tid + 2] = ex + l0 + l1;
    cnt[4 * tid + 3] = ex + l0 + l1 + l2;
    __syncthreads();

#pragma unroll
    for (int i = 0; i < 8; i++) {
        int n = tid + i * 1024;
        int pos = atomicAdd(&cnt[cell8[i]], 1);
        g_sx[b * NPTS + pos] = X[n];
        g_sy[b * NPTS + pos] = Y[n];
        g_sz[b * NPTS + pos] = Z[n];
        g_si[b * NPTS + pos] = n;
    }
}

// ---------------------------------------------------------------------------
// Kernel 0.5: per-point layer-1 pre-activation (no relu):
//   prept[p] = W1c*p + W1f*f(p) + b1. One thread per point, coalesced loads.
// ---------------------------------------------------------------------------
__global__ __launch_bounds__(256, 3) void prept_kernel(
    const float* __restrict__ coords, const float* __restrict__ feats)
{
    extern __shared__ float sm[];           // w1t (2240) + b1 (64)
    const int tid = threadIdx.x;
    for (int i = tid; i < 560; i += 256)
        ((float4*)sm)[i] = ((const float4*)g_w)[i];
    if (tid < 64) sm[2240 + tid] = g_w[14528 + tid];
    __syncthreads();

    const int ng = blockIdx.x * 256 + tid;   // global point id = b*NPTS + n
    const int b = ng >> 13, n = ng & (NPTS - 1);
    const float* X = coords + (size_t)b * 3 * NPTS;
    const float* F = feats + (size_t)b * CF * NPTS;

    float in[35];
    in[0] = X[n];
    in[1] = X[NPTS + n];
    in[2] = X[2 * NPTS + n];
#pragma unroll
    for (int c = 0; c < CF; c++) in[3 + c] = F[c * NPTS + n];

    const ull* bp = (const ull*)(sm + 2240);
    ull* O = g_pp + (size_t)ng * 32;

#pragma unroll
    for (int half = 0; half < 2; half++) {
        ull acc[16];
#pragma unroll
        for (int i = 0; i < 16; i++) acc[i] = bp[half * 16 + i];
#pragma unroll
        for (int c = 0; c < 35; c++) {
            const ull xx = f2pack(in[c], in[c]);
            const ulonglong2* pw = (const ulonglong2*)(sm + c * 64 + half * 32);
#pragma unroll
            for (int i = 0; i < 8; i++) {
                const ulonglong2 w = pw[i];
                F2FMA(acc[2 * i],     w.x, xx, acc[2 * i]);
                F2FMA(acc[2 * i + 1], w.y, xx, acc[2 * i + 1]);
            }
        }
#pragma unroll
        for (int i2 = 0; i2 < 8; i2++) {
            ulonglong2 v; v.x = acc[2 * i2]; v.y = acc[2 * i2 + 1];
            ((ulonglong2*)O)[half * 8 + i2] = v;
        }
    }
}

// ---------------------------------------------------------------------------
// Kernel 1: furthest point sampling (round-12 proven config, untouched).
// ---------------------------------------------------------------------------
__global__ __launch_bounds__(512, 1) void fps_kernel(
    const float* __restrict__ coords, float* __restrict__ centers)
{
    extern __shared__ float smc[];           // [3*NPTS] coords + skey tail
    const int b = blockIdx.x, tid = threadIdx.x;
    const int wid = tid >> 5, lane = tid & 31;
    const float* X = coords + (size_t)b * 3 * NPTS;
    const float* Y = X + NPTS;
    const float* Z = X + 2 * NPTS;
    const float* SX = g_sx + b * NPTS;
    const float* SY = g_sy + b * NPTS;
    const float* SZ = g_sz + b * NPTS;
    const int*   SI = g_si + b * NPTS;

    for (int i = tid; i < (3 * NPTS) / 4; i += 512)
        ((float4*)smc)[i] = ((const float4*)X)[i];
    const float* smx = smc;
    const float* smy = smc + NPTS;
    const float* smz = smc + 2 * NPTS;
    ull* skey = (ull*)(smc + 3 * NPTS);      // [2][16]

    ull px2[8], py2[8], pz2[8];
    int oi[16];
    float dl[16];
    float bxmin = 1e30f, bxmax = -1e30f, bymin = 1e30f, bymax = -1e30f,
          bzmin = 1e30f, bzmax = -1e30f;
    const int base = tid * 16;
#pragma unroll
    for (int j = 0; j < 8; j++) {
        float x0 = SX[base + 2*j], x1 = SX[base + 2*j + 1];
        float y0 = SY[base + 2*j], y1 = SY[base + 2*j + 1];
        float z0 = SZ[base + 2*j], z1 = SZ[base + 2*j + 1];
        px2[j] = f2pack(x0, x1); py2[j] = f2pack(y0, y1); pz2[j] = f2pack(z0, z1);
        oi[2*j] = SI[base + 2*j]; oi[2*j + 1] = SI[base + 2*j + 1];
        dl[2*j] = 1e30f; dl[2*j + 1] = 1e30f;
        bxmin = fminf(bxmin, fminf(x0, x1)); bxmax = fmaxf(bxmax, fmaxf(x0, x1));
        bymin = fminf(bymin, fminf(y0, y1)); bymax = fmaxf(bymax, fmaxf(y0, y1));
        bzmin = fminf(bzmin, fminf(z0, z1)); bzmax = fmaxf(bzmax, fmaxf(z0, z1));
    }

    float* ox = centers + (size_t)b * 3 * M;
    float* oy = ox + M;
    float* oz = ox + 2 * M;

    float cx = __ldg(X), cy = __ldg(Y), cz = __ldg(Z);
    if (tid == 0) { ox[0] = cx; oy[0] = cy; oz[0] = cz; }

    float bm = 1e30f;
    int   bi = 0x7fffffff;

    for (int s = 0; s < M; s++) {
        float tx = fmaxf(fmaxf(bxmin - cx, cx - bxmax), 0.0f);
        float ty = fmaxf(fmaxf(bymin - cy, cy - bymax), 0.0f);
        float tz = fmaxf(fmaxf(bzmin - cz, cz - bzmax), 0.0f);
        float lb2 = fmaf(tz, tz, fmaf(ty, ty, tx * tx));

        if (!(lb2 * 0.999f > bm)) {
            const ull ncx = f2pack(-cx, -cx);
            const ull ncy = f2pack(-cy, -cy);
            const ull ncz = f2pack(-cz, -cz);
#pragma unroll
            for (int j = 0; j < 8; j++) {
                ull dx, dy, dz, t;
                F2ADD(dx, px2[j], ncx);
                F2ADD(dy, py2[j], ncy);
                F2ADD(dz, pz2[j], ncz);
                F2MUL(t, dx, dx);
                F2FMA(t, dy, dy, t);
                F2FMA(t, dz, dz, t);
                float t0, t1; f2unpack(t, t0, t1);
                dl[2*j]     = fminf(dl[2*j],     t0);
                dl[2*j + 1] = fminf(dl[2*j + 1], t1);
            }
            float m0 = fmaxf(dl[0],  dl[1]),  m1 = fmaxf(dl[2],  dl[3]);
            float m2 = fmaxf(dl[4],  dl[5]),  m3 = fmaxf(dl[6],  dl[7]);
            float m4 = fmaxf(dl[8],  dl[9]),  m5 = fmaxf(dl[10], dl[11]);
            float m6 = fmaxf(dl[12], dl[13]), m7 = fmaxf(dl[14], dl[15]);
            m0 = fmaxf(m0, m1); m2 = fmaxf(m2, m3);
            m4 = fmaxf(m4, m5); m6 = fmaxf(m6, m7);
            m0 = fmaxf(m0, m2); m4 = fmaxf(m4, m6);
            bm = fmaxf(m0, m4);
            int mi = 0x7fffffff;
#pragma unroll
            for (int k = 0; k < 16; k++)
                if (dl[k] == bm) mi = min(mi, oi[k]);
            bi = mi;
        }

        unsigned mb = __float_as_uint(bm);
        unsigned wm = redux_max_u32(mb);
        unsigned ci = (mb == wm) ? (unsigned)bi : 0x7fffffffu;
        unsigned wi = redux_min_u32(ci);
        if (lane == 0) skey[(s & 1) * 16 + wid] = ((ull)wm << 32) | wi;
        __syncthreads();

        ull k = skey[(s & 1) * 16 + (lane & 15)];
        unsigned v  = (unsigned)(k >> 32);
        unsigned ii = (unsigned)k;
        unsigned gm = redux_max_u32(v);
        unsigned c2 = (v == gm) ? ii : 0x7fffffffu;
        unsigned gi = redux_min_u32(c2);

        cx = smx[gi]; cy = smy[gi]; cz = smz[gi];
        if (tid == 0 && s + 1 < M) {
            ox[s + 1] = cx; oy[s + 1] = cy; oz[s + 1] = cz;
        }
    }
}

// ---------------------------------------------------------------------------
// Kernel 2: ball query (round-12 proven config, untouched).
// ---------------------------------------------------------------------------
__global__ __launch_bounds__(128) void bq_kernel(
    const float* __restrict__ coords, const float* __restrict__ centers)
{
    const int gw   = (blockIdx.x * blockDim.x + threadIdx.x) >> 5;
    const int lane = threadIdx.x & 31;
    if (gw >= BATCH * M) return;
    const int b = gw >> 11, m = gw & (M - 1);

    const float* X = coords + (size_t)b * 3 * NPTS;
    const float* Y = X + NPTS;
    const float* Z = X + 2 * NPTS;
    const float* C = centers + (size_t)b * 3 * M;
    const float cx = C[m], cy = C[M + m], cz = C[2 * M + m];

    const int base = gw * KNN;
    int cnt = 0, firstn = 0;

    for (int c0 = 0; c0 < NPTS && cnt < KNN; c0 += 128) {
        unsigned msk[4];
#pragma unroll
        for (int u = 0; u < 4; u++) {
            const int n = c0 + u * 32 + lane;
            float dx = X[n] - cx, dy = Y[n] - cy, dz = Z[n] - cz;
            float d2 = fmaf(dz, dz, fmaf(dy, dy, dx * dx));
            msk[u] = __ballot_sync(0xffffffffu, d2 < R2);
        }
#pragma unroll
        for (int u = 0; u < 4; u++) {
            if (cnt < KNN) {
                const unsigned mask = msk[u];
                const int n = c0 + u * 32 + lane;
                if (cnt == 0 && mask) firstn = c0 + u * 32 + __ffs(mask) - 1;
                bool hit = (mask >> lane) & 1u;
                int pos = cnt + __popc(mask & ((1u << lane) - 1u));
                if (hit && pos < KNN) g_idx[base + pos] = n;
                cnt += __popc(mask);
            }
        }
    }
    for (int j = cnt + lane; j < KNN; j += 32) g_idx[base + j] = firstn;
}

// ---------------------------------------------------------------------------
// Kernel 3: full MLP consumer. Warp = center, lane = neighbor.
//   h1 = relu(prept[b*NPTS+idx] + (-W1c*c)); then layer2 + layer3 + maxpool.
// ---------------------------------------------------------------------------
__global__ __launch_bounds__(256, 2) void mlp2_kernel(
    const float* __restrict__ centers, float* __restrict__ out)
{
    extern __shared__ float sm[];
    const int tid = threadIdx.x;
    for (int i = tid; i < 3136; i += 256)
        ((float4*)sm)[i] = ((const float4*)(g_w + 2240))[i];
    if (tid < 48)                              // w1 rows 0..2 (w1c) -> tail
        ((float4*)(sm + 12544))[tid] = ((const float4*)g_w)[tid];
    __syncthreads();

    float* w2t = sm;                 // [64][64]
    float* w3t = sm + 4096;          // [64][128]
    const ull* bias2 = (const ull*)(sm + 12352);
    const ull* bias3 = (const ull*)(sm + 12416);
    const float* w1c = sm + 12544;   // [3][64]

    const int wid = tid >> 5, lane = tid & 31;
    const int gw = blockIdx.x * 8 + wid;
    const int b = gw >> 11, m = gw & (M - 1);

    const float* C = centers + (size_t)b * 3 * M;
    const float cx = C[m], cy = C[M + m], cz = C[2 * M + m];

    // center term: lane holds channel-pair 'lane' of (-W1c*c)
    ull pcv;
    {
        const ull w0 = ((const ull*)(w1c))[lane];
        const ull w1 = ((const ull*)(w1c + 64))[lane];
        const ull w2 = ((const ull*)(w1c + 128))[lane];
        F2MUL(pcv, w0, f2pack(-cx, -cx));
        F2FMA(pcv, w1, f2pack(-cy, -cy), pcv);
        F2FMA(pcv, w2, f2pack(-cz, -cz), pcv);
    }

    const int idx = g_idx[gw * KNN + lane];
    const ulonglong2* PP =
        (const ulonglong2*)(g_pp + ((size_t)(b * NPTS + idx)) * 32);  // FIX: batch offset

    ull acc[32];
#pragma unroll
    for (int i = 0; i < 32; i++) acc[i] = bias2[i];

    for (int blk = 0; blk < 4; blk++) {
        ulonglong2 pp2[4];
#pragma unroll
        for (int t2 = 0; t2 < 4; t2++) pp2[t2] = PP[blk * 4 + t2];
#pragma unroll
        for (int t = 0; t < 8; t++) {
            ull ppv = (t & 1) ? pp2[t >> 1].y : pp2[t >> 1].x;
            ull pv  = __shfl_sync(0xffffffffu, pcv, blk * 8 + t);
            ull hv; F2ADD(hv, ppv, pv);
            float x0, x1; f2unpack(hv, x0, x1);
            x0 = fmaxf(x0, 0.f); x1 = fmaxf(x1, 0.f);
            const ull xx0 = f2pack(x0, x0), xx1 = f2pack(x1, x1);
            const int c = blk * 16 + 2 * t;
            const ulonglong2* pw0 = (const ulonglong2*)(w2t + c * 64);
            const ulonglong2* pw1 = (const ulonglong2*)(w2t + (c + 1) * 64);
#pragma unroll
            for (int i = 0; i < 16; i++) {
                const ulonglong2 w = pw0[i];
                F2FMA(acc[2 * i],     w.x, xx0, acc[2 * i]);
                F2FMA(acc[2 * i + 1], w.y, xx0, acc[2 * i + 1]);
            }
#pragma unroll
            for (int i = 0; i < 16; i++) {
                const ulonglong2 w = pw1[i];
                F2FMA(acc[2 * i],     w.x, xx1, acc[2 * i]);
                F2FMA(acc[2 * i + 1], w.y, xx1, acc[2 * i + 1]);
            }
        }
    }

    float h2[64];
#pragma unroll
    for (int i = 0; i < 32; i++) {
        float a, c2; f2unpack(acc[i], a, c2);
        h2[2 * i] = fmaxf(a, 0.f); h2[2 * i + 1] = fmaxf(c2, 0.f);
    }

    float* O = out + (size_t)b * 128 * M + m;
    for (int q = 0; q < 4; q++) {
        ull a3[16];
#pragma unroll
        for (int i = 0; i < 16; i++) a3[i] = bias3[q * 16 + i];
#pragma unroll
        for (int c = 0; c < 64; c++) {
            const ull xx = f2pack(h2[c], h2[c]);
            const ulonglong2* pw = (const ulonglong2*)(w3t + c * 128 + q * 32);
#pragma unroll
            for (int i = 0; i < 8; i++) {
                const ulonglong2 w = pw[i];
                F2FMA(a3[2 * i],     w.x, xx, a3[2 * i]);
                F2FMA(a3[2 * i + 1], w.y, xx, a3[2 * i + 1]);
            }
        }
#pragma unroll
        for (int i = 0; i < 16; i++) {
            float u, v; f2unpack(a3[i], u, v);
            u = fmaxf(u, 0.f); v = fmaxf(v, 0.f);
#pragma unroll
            for (int off = 16; off; off >>= 1) {
                u = fmaxf(u, __shfl_xor_sync(0xffffffffu, u, off));
                v = fmaxf(v, __shfl_xor_sync(0xffffffffu, v, off));
            }
            if (lane == 0) {
                O[(q * 32 + 2 * i) * M]     = u;
                O[(q * 32 + 2 * i + 1) * M] = v;
            }
        }
    }
}

// ---------------------------------------------------------------------------
extern "C" void kernel_launch(void* const* d_in, const int* in_sizes, int n_in,
                              void* d_out, int out_size)
{
    const float* feats  = (const float*)d_in[0];
    const float* coords = (const float*)d_in[1];
    const float* W1 = (const float*)d_in[2];
    const float* B1 = (const float*)d_in[3];
    const float* W2 = (const float*)d_in[4];
    const float* B2 = (const float*)d_in[5];
    const float* W3 = (const float*)d_in[6];
    const float* B3 = (const float*)d_in[7];

    float* out     = (float*)d_out;
    float* centers = out + (size_t)BATCH * 128 * M;

    sort_kernel<<<BATCH + (WTOT + 1023) / 1024, 1024>>>(
        coords, W1, B1, W2, B2, W3, B3);

    prept_kernel<<<(BATCH * NPTS) / 256, 256, 2304 * 4>>>(coords, feats);

    const int SMEMF = (3 * NPTS) * 4 + 2 * 16 * 8;
    cudaFuncSetAttribute(fps_kernel, cudaFuncAttributeMaxDynamicSharedMemorySize, SMEMF);
    fps_kernel<<<BATCH, 512, SMEMF>>>(coords, centers);

    bq_kernel<<<(BATCH * M) / 4, 128>>>(coords, centers);

    const int SMEM2 = 12736 * 4;
    cudaFuncSetAttribute(mlp2_kernel, cudaFuncAttributeMaxDynamicSharedMemorySize, SMEM2);
    mlp2_kernel<<<(BATCH * M) / 8, 256, SMEM2>>>(centers, out);
}